// round 15
// baseline (speedup 1.0000x reference)
#include <cuda_runtime.h>
#include <cuda_bf16.h>

#define NN 10
#define DD 64
#define MS 72
#define PF 4                               // W matrices prefetched per step

__device__ float g_M9[DD][DD];            // out = x @ g_M9 + g_dv9
__device__ float g_dv9[DD];
__device__ volatile unsigned g_flag;      // precompute-done counter (0..33)
__device__ unsigned g_done;               // gemm-block completion counter

typedef unsigned long long ull;

__device__ __forceinline__ unsigned tf32_rna(float v) {
    unsigned u = __float_as_uint(v);
    return (u + 0x1000u) & 0xFFFFE000u;
}

__device__ __forceinline__ void mma_tf32(float& c0, float& c1, float& c2, float& c3,
                                         unsigned a0, unsigned a1, unsigned a2, unsigned a3,
                                         unsigned b0, unsigned b1) {
    asm volatile(
        "mma.sync.aligned.m16n8k8.row.col.f32.tf32.tf32.f32 "
        "{%0,%1,%2,%3}, {%4,%5,%6,%7}, {%8,%9}, {%0,%1,%2,%3};"
        : "+f"(c0), "+f"(c1), "+f"(c2), "+f"(c3)
        : "r"(a0), "r"(a1), "r"(a2), "r"(a3), "r"(b0), "r"(b1));
}

__device__ __forceinline__ ull ffma2(ull a, ull b, ull c) {
    ull d;
    asm("fma.rn.f32x2 %0, %1, %2, %3;" : "=l"(d) : "l"(a), "l"(b), "l"(c));
    return d;
}
__device__ __forceinline__ ull fdup(float v) {
    ull d;
    asm("mov.b64 %0, {%1, %1};" : "=l"(d) : "f"(v));
    return d;
}
__device__ __forceinline__ void cp16(unsigned smem_addr, const void* gptr) {
    asm volatile("cp.async.ca.shared.global [%0], [%1], 16;"
                 :: "r"(smem_addr), "l"(gptr));
}

// ---- precompute role: blocks 0..32 ------------------------------------------
// FFMA2 col-pair layout + cp.async smem prefetch of next step's W (f<=PF).
__device__ void precompute_role(const float* __restrict__ W,
                                const float* __restrict__ B,
                                float* sh, int bi) {
    float* rowsh = sh;                    // [NN][2][DD]   = 1280 floats
    float* red   = sh + 1280;             // [8][2][DD]    = 1024 floats
    float* wbuf  = sh + 2304;             // [PF][4096]    = 64 KB
    const int tid  = threadIdx.x;
    const bool bias = (bi == 32);
    const int d0   = bi * 2;
    const int kk   = tid >> 5;            // 0..7: k-seg of 8 (constant per warp)
    const int hp   = tid & 31;            // col pair 2hp, 2hp+1
    const int rr   = tid >> 6;            // 0..1 (tid < 128)
    const int hh   = tid & 63;
    const unsigned wb_base = (unsigned)__cvta_generic_to_shared(wbuf);

    if (tid < 128)
        rowsh[(0 * 2 + rr) * DD + hh] = (!bias && (d0 + rr == hh)) ? 1.f : 0.f;
    __syncthreads();

    #pragma unroll
    for (int t = 1; t <= 9; ++t) {
        // extra term (f = 0 contribution / summed biases)
        float extra = 0.f;
        if (tid < 128) {
            if (!bias) {
                extra = W[((size_t)t * DD + (d0 + rr)) * DD + hh];    // W[0,t][d,h]
            } else if (rr == 0) {
                #pragma unroll
                for (int f = 0; f < t; ++f)
                    extra += B[((size_t)f * NN + t) * DD + hh];
            }
        }

        // ---- FMA phase: packed f32x2 over the col pair ----
        ull acc0 = 0ull, acc1 = 0ull;
        #pragma unroll
        for (int f = 1; f < t; ++f) {
            const float* src = (f <= PF) ? (wbuf + (f - 1) * 4096)
                                         : (W + ((size_t)f * NN + t) * 4096);
            #pragma unroll
            for (int k = 0; k < 8; ++k) {
                const int ki = kk * 8 + k;
                ull w2 = *reinterpret_cast<const ull*>(src + ki * DD + 2 * hp);
                acc0 = ffma2(fdup(rowsh[(f * 2 + 0) * DD + ki]), w2, acc0);
                acc1 = ffma2(fdup(rowsh[(f * 2 + 1) * DD + ki]), w2, acc1);
            }
        }
        *reinterpret_cast<ull*>(&red[(kk * 2 + 0) * DD + 2 * hp]) = acc0;
        *reinterpret_cast<ull*>(&red[(kk * 2 + 1) * DD + 2 * hp]) = acc1;
        __syncthreads();   // partials visible; wbuf reads of this step done

        // ---- issue cp.async prefetch of step t+1's W (f = 1..min(t,PF)) ----
        if (t < 9) {
            const int nf = (t < PF) ? t : PF;
            #pragma unroll
            for (int f = 1; f <= PF; ++f) {
                if (f <= nf) {
                    const float* gsrc = W + ((size_t)f * NN + (t + 1)) * 4096 + tid * 16;
                    unsigned daddr = wb_base + ((f - 1) * 4096 + tid * 16) * 4;
                    cp16(daddr +  0, gsrc +  0);
                    cp16(daddr + 16, gsrc +  4);
                    cp16(daddr + 32, gsrc +  8);
                    cp16(daddr + 48, gsrc + 12);
                }
            }
            asm volatile("cp.async.commit_group;");
        }

        // ---- reduction over the 8 k-segments ----
        if (tid < 128) {
            float s = extra;
            #pragma unroll
            for (int k2 = 0; k2 < 8; ++k2) s += red[(k2 * 2 + rr) * DD + hh];
            rowsh[(t * 2 + rr) * DD + hh] = s;
            if (t == 9) {
                if (!bias)        g_M9[d0 + rr][hh] = s;
                else if (rr == 0) g_dv9[hh] = s;
            }
        }
        if (t < 9) asm volatile("cp.async.wait_group 0;");
        __syncthreads();   // prefetched W + rowsh[t] visible to all
    }

    __threadfence();
    __syncthreads();
    if (tid == 0) atomicAdd((unsigned*)&g_flag, 1u);
}

// ---- gemm role: blocks 33..288, 256 rows each (R9 form: 23.0 baseline) ------
__device__ void gemm_role(const float* __restrict__ x, float* __restrict__ out,
                          unsigned* shb, int bid) {
    unsigned* Msm = shb;                                  // [64][MS]
    unsigned* xs2 = shb + 64 * MS;                        // [128][MS] tf32 half-2 rows
    float*    dvs = reinterpret_cast<float*>(xs2 + 128 * MS);
    const int tid  = threadIdx.x;
    const int w    = tid >> 5;
    const int lane = tid & 31;
    const int g    = lane >> 2;
    const int t    = lane & 3;
    const int R0   = bid * 256;
    const int rowA = R0 + w * 16 + g;                     // half-1 rows: rowA, rowA+8

    // ---- pre-wake 1: half-1 A fragments into registers ----
    unsigned af1[8][4];
    {
        const float2* a0p = reinterpret_cast<const float2*>(x + (size_t)rowA * DD);
        const float2* a1p = reinterpret_cast<const float2*>(x + (size_t)(rowA + 8) * DD);
        #pragma unroll
        for (int k8 = 0; k8 < 8; ++k8) {
            float2 v0 = a0p[4 * k8 + t];
            float2 v1 = a1p[4 * k8 + t];
            af1[k8][0] = tf32_rna(v0.x); af1[k8][2] = tf32_rna(v0.y);
            af1[k8][1] = tf32_rna(v1.x); af1[k8][3] = tf32_rna(v1.y);
        }
    }
    // ---- pre-wake 2: half-2 rows tf32-staged into shared ----
    {
        const int r    = tid >> 1;
        const int half = tid & 1;
        const float4* src = reinterpret_cast<const float4*>(
            x + (size_t)(R0 + 128 + r) * DD + half * 32);
        #pragma unroll
        for (int i = 0; i < 8; ++i) {
            float4 v = src[i];
            uint4 u = make_uint4(tf32_rna(v.x), tf32_rna(v.y), tf32_rna(v.z), tf32_rna(v.w));
            *reinterpret_cast<uint4*>(&xs2[r * MS + half * 32 + 4 * i]) = u;
        }
    }

    // ---- wait: single-thread spin, rest park at the barrier ----
    if (tid == 0) {
        while (g_flag < 33u) __nanosleep(64);
        __threadfence();
    }
    __syncthreads();

    // ---- stage M^T + bias ----
    {
        const float* Mflat = &g_M9[0][0];
        #pragma unroll
        for (int i = 0; i < 16; ++i) {
            int idx = i * 256 + tid;
            int k = idx >> 6, n = idx & 63;
            Msm[n * MS + k] = tf32_rna(Mflat[idx]);
        }
        if (tid < 64) dvs[tid] = g_dv9[tid];
    }
    __syncthreads();

    float2 dvp[8];
    #pragma unroll
    for (int n = 0; n < 8; ++n)
        dvp[n] = *reinterpret_cast<const float2*>(&dvs[8 * n + 2 * t]);

    // ---- half 1: A from registers ----
    {
        float acc[8][4];
        #pragma unroll
        for (int n = 0; n < 8; ++n)
            #pragma unroll
            for (int c = 0; c < 4; ++c) acc[n][c] = 0.f;
        #pragma unroll
        for (int k8 = 0; k8 < 8; ++k8) {
            const int kcol = 8 * k8 + 2 * t;
            #pragma unroll
            for (int n = 0; n < 8; ++n) {
                uint2 bf = *reinterpret_cast<const uint2*>(&Msm[(8 * n + g) * MS + kcol]);
                mma_tf32(acc[n][0], acc[n][1], acc[n][2], acc[n][3],
                         af1[k8][0], af1[k8][1], af1[k8][2], af1[k8][3], bf.x, bf.y);
            }
        }
        #pragma unroll
        for (int n = 0; n < 8; ++n) {
            float2 o0 = make_float2(acc[n][0] + dvp[n].x, acc[n][1] + dvp[n].y);
            float2 o1 = make_float2(acc[n][2] + dvp[n].x, acc[n][3] + dvp[n].y);
            *reinterpret_cast<float2*>(out + (size_t)rowA * DD + 8 * n + 2 * t)       = o0;
            *reinterpret_cast<float2*>(out + (size_t)(rowA + 8) * DD + 8 * n + 2 * t) = o1;
        }
    }
    // ---- half 2: A fragments from shared (conflict-free LDS.64) ----
    {
        const int lr = w * 16 + g;
        float acc[8][4];
        #pragma unroll
        for (int n = 0; n < 8; ++n)
            #pragma unroll
            for (int c = 0; c < 4; ++c) acc[n][c] = 0.f;
        #pragma unroll
        for (int k8 = 0; k8 < 8; ++k8) {
            const int kcol = 8 * k8 + 2 * t;
            uint2 a0 = *reinterpret_cast<const uint2*>(&xs2[lr * MS + kcol]);
            uint2 a1 = *reinterpret_cast<const uint2*>(&xs2[(lr + 8) * MS + kcol]);
            #pragma unroll
            for (int n = 0; n < 8; ++n) {
                uint2 bf = *reinterpret_cast<const uint2*>(&Msm[(8 * n + g) * MS + kcol]);
                mma_tf32(acc[n][0], acc[n][1], acc[n][2], acc[n][3],
                         a0.x, a1.x, a0.y, a1.y, bf.x, bf.y);
            }
        }
        const int rowB = R0 + 128 + lr;
        #pragma unroll
        for (int n = 0; n < 8; ++n) {
            float2 o0 = make_float2(acc[n][0] + dvp[n].x, acc[n][1] + dvp[n].y);
            float2 o1 = make_float2(acc[n][2] + dvp[n].x, acc[n][3] + dvp[n].y);
            *reinterpret_cast<float2*>(out + (size_t)rowB * DD + 8 * n + 2 * t)       = o0;
            *reinterpret_cast<float2*>(out + (size_t)(rowB + 8) * DD + 8 * n + 2 * t) = o1;
        }
    }

    // ---- replay hygiene: last gemm block resets the counters ----
    __syncthreads();
    if (tid == 0) {
        unsigned v = atomicAdd(&g_done, 1u);
        if (v == 255u) {
            g_done = 0u;
            g_flag = 0u;
            __threadfence();
        }
    }
}

__global__ __launch_bounds__(256, 2) void fused_kernel(const float* __restrict__ x,
                                                       const float* __restrict__ W,
                                                       const float* __restrict__ B,
                                                       float* __restrict__ out) {
    extern __shared__ __align__(16) float sh[];
    if (blockIdx.x < 33)
        precompute_role(W, B, sh, blockIdx.x);
    else
        gemm_role(x, out, reinterpret_cast<unsigned*>(sh), blockIdx.x - 33);
}

extern "C" void kernel_launch(void* const* d_in, const int* in_sizes, int n_in,
                              void* d_out, int out_size) {
    const float* x = (const float*)d_in[0];
    const float* W = (const float*)d_in[1];
    const float* b = (const float*)d_in[2];
    float* out = (float*)d_out;

    // precompute: 2304 floats + 64KB wbuf = 74752B; gemm needs 55552B -> max
    const int smem_bytes = 2304 * 4 + PF * 4096 * 4;      // 74752
    cudaFuncSetAttribute(fused_kernel, cudaFuncAttributeMaxDynamicSharedMemorySize, smem_bytes);

    fused_kernel<<<289, 256, smem_bytes>>>(x, W, b, out);
}

// round 16
// speedup vs baseline: 1.1263x; 1.1263x over previous
#include <cuda_runtime.h>
#include <cuda_bf16.h>

#define NN 10
#define DD 64
#define MS 72
#define PF 6                               // W matrices resident in smem ring

__device__ float g_M9[DD][DD];            // out = x @ g_M9 + g_dv9
__device__ float g_dv9[DD];
__device__ volatile unsigned g_flag;      // precompute-done counter (0..33)
__device__ unsigned g_done;               // gemm-block completion counter

__device__ __forceinline__ unsigned tf32_rna(float v) {
    unsigned u = __float_as_uint(v);
    return (u + 0x1000u) & 0xFFFFE000u;
}

__device__ __forceinline__ void mma_tf32(float& c0, float& c1, float& c2, float& c3,
                                         unsigned a0, unsigned a1, unsigned a2, unsigned a3,
                                         unsigned b0, unsigned b1) {
    asm volatile(
        "mma.sync.aligned.m16n8k8.row.col.f32.tf32.tf32.f32 "
        "{%0,%1,%2,%3}, {%4,%5,%6,%7}, {%8,%9}, {%0,%1,%2,%3};"
        : "+f"(c0), "+f"(c1), "+f"(c2), "+f"(c3)
        : "r"(a0), "r"(a1), "r"(a2), "r"(a3), "r"(b0), "r"(b1));
}

// ---- precompute role: blocks 0..32 ------------------------------------------
// R8 math; W served from a smem ring filled by cp.async.bulk (one 16KB bulk
// per matrix, issued by tid 0, completion via mbarrier). Steps 2..7 fully
// load-hidden; t=8,9 direct-load only f=7,8.
__device__ void precompute_role(const float* __restrict__ W,
                                const float* __restrict__ B,
                                float* sh, int bi) {
    float*              rowsh = sh;                 // [NN][2][DD] = 1280
    float*              red   = sh + 1280;          // [16][2][DD] = 2048
    unsigned long long* mbar  = reinterpret_cast<unsigned long long*>(sh + 3328);
    float*              wbuf  = sh + 3332;          // [PF][4096], 16B aligned
    const int tid  = threadIdx.x;
    const bool bias = (bi == 32);
    const int d0   = bi * 2;
    const int kk   = tid >> 4;
    const int hg   = tid & 15;
    const int rr   = tid >> 6;
    const int hh   = tid & 63;
    const unsigned mbar_a = (unsigned)__cvta_generic_to_shared(mbar);
    const unsigned wb_a   = (unsigned)__cvta_generic_to_shared(wbuf);

    if (tid < 128)
        rowsh[(0 * 2 + rr) * DD + hh] = (!bias && (d0 + rr == hh)) ? 1.f : 0.f;
    if (tid == 0)
        asm volatile("mbarrier.init.shared.b64 [%0], 1;" :: "r"(mbar_a) : "memory");
    __syncthreads();

    #pragma unroll
    for (int t = 1; t <= 9; ++t) {
        // ---- wait for W[*,t] prefetched during step t-1 ----
        if (t >= 2) {
            const unsigned par = (unsigned)((t - 2) & 1);
            unsigned done;
            asm volatile(
                "{\n\t.reg .pred p;\n\t"
                "mbarrier.try_wait.parity.shared.b64 p, [%1], %2;\n\t"
                "selp.b32 %0, 1, 0, p;\n\t}"
                : "=r"(done) : "r"(mbar_a), "r"(par) : "memory");
            while (!done) {
                asm volatile(
                    "{\n\t.reg .pred p;\n\t"
                    "mbarrier.try_wait.parity.shared.b64 p, [%1], %2, 0x989680;\n\t"
                    "selp.b32 %0, 1, 0, p;\n\t}"
                    : "=r"(done) : "r"(mbar_a), "r"(par) : "memory");
            }
        }

        float extra = 0.f;
        if (tid < 128) {
            if (!bias) {
                extra = W[((size_t)t * DD + (d0 + rr)) * DD + hh];    // W[0,t][d,h]
            } else if (rr == 0) {
                #pragma unroll
                for (int f = 0; f < t; ++f)
                    extra += B[((size_t)f * NN + t) * DD + hh];
            }
        }

        float4 a0 = make_float4(0.f, 0.f, 0.f, 0.f);
        float4 a1 = make_float4(0.f, 0.f, 0.f, 0.f);

        #pragma unroll
        for (int f = 1; f < t; ++f) {
            const float* src = (f <= PF) ? (wbuf + (f - 1) * 4096 + (kk * 4) * DD + hg * 4)
                                         : (W + ((size_t)f * NN + t) * 4096 + (kk * 4) * DD + hg * 4);
            float4 w0 = *reinterpret_cast<const float4*>(src + 0 * DD);
            float4 w1 = *reinterpret_cast<const float4*>(src + 1 * DD);
            float4 w2 = *reinterpret_cast<const float4*>(src + 2 * DD);
            float4 w3 = *reinterpret_cast<const float4*>(src + 3 * DD);
            float4 r0 = *reinterpret_cast<const float4*>(&rowsh[(f * 2 + 0) * DD + kk * 4]);
            float4 r1 = *reinterpret_cast<const float4*>(&rowsh[(f * 2 + 1) * DD + kk * 4]);
            a0.x += r0.x * w0.x + r0.y * w1.x + r0.z * w2.x + r0.w * w3.x;
            a0.y += r0.x * w0.y + r0.y * w1.y + r0.z * w2.y + r0.w * w3.y;
            a0.z += r0.x * w0.z + r0.y * w1.z + r0.z * w2.z + r0.w * w3.z;
            a0.w += r0.x * w0.w + r0.y * w1.w + r0.z * w2.w + r0.w * w3.w;
            a1.x += r1.x * w0.x + r1.y * w1.x + r1.z * w2.x + r1.w * w3.x;
            a1.y += r1.x * w0.y + r1.y * w1.y + r1.z * w2.y + r1.w * w3.y;
            a1.z += r1.x * w0.z + r1.y * w1.z + r1.z * w2.z + r1.w * w3.z;
            a1.w += r1.x * w0.w + r1.y * w1.w + r1.z * w2.w + r1.w * w3.w;
        }
        *reinterpret_cast<float4*>(&red[(kk * 2 + 0) * DD + hg * 4]) = a0;
        *reinterpret_cast<float4*>(&red[(kk * 2 + 1) * DD + hg * 4]) = a1;
        __syncthreads();   // partials visible; wbuf reads of this step complete

        // ---- prefetch W[f, t+1] (f = 1..min(t,PF)) via cp.async.bulk ----
        if (t < 9 && tid == 0) {
            const int nf = (t < PF) ? t : PF;
            asm volatile("mbarrier.arrive.expect_tx.shared.b64 _, [%0], %1;"
                         :: "r"(mbar_a), "r"((unsigned)(nf * 16384)) : "memory");
            for (int f = 1; f <= nf; ++f) {
                const float* gsrc = W + ((size_t)f * NN + (t + 1)) * 4096;
                asm volatile(
                    "cp.async.bulk.shared::cta.global.mbarrier::complete_tx::bytes "
                    "[%0], [%1], %2, [%3];"
                    :: "r"(wb_a + (f - 1) * 16384u), "l"(gsrc),
                       "r"(16384u), "r"(mbar_a) : "memory");
            }
        }

        // ---- reduction over the 16 k-segments ----
        if (tid < 128) {
            float s = extra;
            #pragma unroll
            for (int k2 = 0; k2 < 16; ++k2) s += red[(k2 * 2 + rr) * DD + hh];
            rowsh[(t * 2 + rr) * DD + hh] = s;
            if (t == 9) {
                if (!bias)        g_M9[d0 + rr][hh] = s;
                else if (rr == 0) g_dv9[hh] = s;
            }
        }
        __syncthreads();
    }

    __threadfence();
    __syncthreads();
    if (tid == 0) atomicAdd((unsigned*)&g_flag, 1u);
}

// ---- gemm role: blocks 33..288, 256 rows each (23.0-verified, unchanged) ----
__device__ void gemm_role(const float* __restrict__ x, float* __restrict__ out,
                          unsigned* shb, int bid) {
    unsigned* Msm = shb;                                  // [64][MS]
    unsigned* xs2 = shb + 64 * MS;                        // [128][MS] tf32 half-2 rows
    float*    dvs = reinterpret_cast<float*>(xs2 + 128 * MS);
    const int tid  = threadIdx.x;
    const int w    = tid >> 5;
    const int lane = tid & 31;
    const int g    = lane >> 2;
    const int t    = lane & 3;
    const int R0   = bid * 256;
    const int rowA = R0 + w * 16 + g;                     // half-1 rows: rowA, rowA+8

    // ---- pre-wake 1: half-1 A fragments into registers ----
    unsigned af1[8][4];
    {
        const float2* a0p = reinterpret_cast<const float2*>(x + (size_t)rowA * DD);
        const float2* a1p = reinterpret_cast<const float2*>(x + (size_t)(rowA + 8) * DD);
        #pragma unroll
        for (int k8 = 0; k8 < 8; ++k8) {
            float2 v0 = a0p[4 * k8 + t];
            float2 v1 = a1p[4 * k8 + t];
            af1[k8][0] = tf32_rna(v0.x); af1[k8][2] = tf32_rna(v0.y);
            af1[k8][1] = tf32_rna(v1.x); af1[k8][3] = tf32_rna(v1.y);
        }
    }
    // ---- pre-wake 2: half-2 rows tf32-staged into shared ----
    {
        const int r    = tid >> 1;
        const int half = tid & 1;
        const float4* src = reinterpret_cast<const float4*>(
            x + (size_t)(R0 + 128 + r) * DD + half * 32);
        #pragma unroll
        for (int i = 0; i < 8; ++i) {
            float4 v = src[i];
            uint4 u = make_uint4(tf32_rna(v.x), tf32_rna(v.y), tf32_rna(v.z), tf32_rna(v.w));
            *reinterpret_cast<uint4*>(&xs2[r * MS + half * 32 + 4 * i]) = u;
        }
    }

    // ---- wait: single-thread spin, rest park at the barrier ----
    if (tid == 0) {
        while (g_flag < 33u) __nanosleep(64);
        __threadfence();
    }
    __syncthreads();

    // ---- stage M^T + bias ----
    {
        const float* Mflat = &g_M9[0][0];
        #pragma unroll
        for (int i = 0; i < 16; ++i) {
            int idx = i * 256 + tid;
            int k = idx >> 6, n = idx & 63;
            Msm[n * MS + k] = tf32_rna(Mflat[idx]);
        }
        if (tid < 64) dvs[tid] = g_dv9[tid];
    }
    __syncthreads();

    float2 dvp[8];
    #pragma unroll
    for (int n = 0; n < 8; ++n)
        dvp[n] = *reinterpret_cast<const float2*>(&dvs[8 * n + 2 * t]);

    // ---- half 1: A from registers ----
    {
        float acc[8][4];
        #pragma unroll
        for (int n = 0; n < 8; ++n)
            #pragma unroll
            for (int c = 0; c < 4; ++c) acc[n][c] = 0.f;
        #pragma unroll
        for (int k8 = 0; k8 < 8; ++k8) {
            const int kcol = 8 * k8 + 2 * t;
            #pragma unroll
            for (int n = 0; n < 8; ++n) {
                uint2 bf = *reinterpret_cast<const uint2*>(&Msm[(8 * n + g) * MS + kcol]);
                mma_tf32(acc[n][0], acc[n][1], acc[n][2], acc[n][3],
                         af1[k8][0], af1[k8][1], af1[k8][2], af1[k8][3], bf.x, bf.y);
            }
        }
        #pragma unroll
        for (int n = 0; n < 8; ++n) {
            float2 o0 = make_float2(acc[n][0] + dvp[n].x, acc[n][1] + dvp[n].y);
            float2 o1 = make_float2(acc[n][2] + dvp[n].x, acc[n][3] + dvp[n].y);
            *reinterpret_cast<float2*>(out + (size_t)rowA * DD + 8 * n + 2 * t)       = o0;
            *reinterpret_cast<float2*>(out + (size_t)(rowA + 8) * DD + 8 * n + 2 * t) = o1;
        }
    }
    // ---- half 2: A fragments from shared (conflict-free LDS.64) ----
    {
        const int lr = w * 16 + g;
        float acc[8][4];
        #pragma unroll
        for (int n = 0; n < 8; ++n)
            #pragma unroll
            for (int c = 0; c < 4; ++c) acc[n][c] = 0.f;
        #pragma unroll
        for (int k8 = 0; k8 < 8; ++k8) {
            const int kcol = 8 * k8 + 2 * t;
            uint2 a0 = *reinterpret_cast<const uint2*>(&xs2[lr * MS + kcol]);
            uint2 a1 = *reinterpret_cast<const uint2*>(&xs2[(lr + 8) * MS + kcol]);
            #pragma unroll
            for (int n = 0; n < 8; ++n) {
                uint2 bf = *reinterpret_cast<const uint2*>(&Msm[(8 * n + g) * MS + kcol]);
                mma_tf32(acc[n][0], acc[n][1], acc[n][2], acc[n][3],
                         a0.x, a1.x, a0.y, a1.y, bf.x, bf.y);
            }
        }
        const int rowB = R0 + 128 + lr;
        #pragma unroll
        for (int n = 0; n < 8; ++n) {
            float2 o0 = make_float2(acc[n][0] + dvp[n].x, acc[n][1] + dvp[n].y);
            float2 o1 = make_float2(acc[n][2] + dvp[n].x, acc[n][3] + dvp[n].y);
            *reinterpret_cast<float2*>(out + (size_t)rowB * DD + 8 * n + 2 * t)       = o0;
            *reinterpret_cast<float2*>(out + (size_t)(rowB + 8) * DD + 8 * n + 2 * t) = o1;
        }
    }

    // ---- replay hygiene: last gemm block resets the counters ----
    __syncthreads();
    if (tid == 0) {
        unsigned v = atomicAdd(&g_done, 1u);
        if (v == 255u) {
            g_done = 0u;
            g_flag = 0u;
            __threadfence();
        }
    }
}

__global__ __launch_bounds__(256, 2) void fused_kernel(const float* __restrict__ x,
                                                       const float* __restrict__ W,
                                                       const float* __restrict__ B,
                                                       float* __restrict__ out) {
    extern __shared__ __align__(16) float sh[];
    if (blockIdx.x < 33)
        precompute_role(W, B, sh, blockIdx.x);
    else
        gemm_role(x, out, reinterpret_cast<unsigned*>(sh), blockIdx.x - 33);
}

extern "C" void kernel_launch(void* const* d_in, const int* in_sizes, int n_in,
                              void* d_out, int out_size) {
    const float* x = (const float*)d_in[0];
    const float* W = (const float*)d_in[1];
    const float* b = (const float*)d_in[2];
    float* out = (float*)d_out;

    // precompute: (3332 + PF*4096)*4 = 111632 B; gemm needs 55552 B -> max
    const int smem_bytes = (3332 + PF * 4096) * 4;
    cudaFuncSetAttribute(fused_kernel, cudaFuncAttributeMaxDynamicSharedMemorySize, smem_bytes);

    fused_kernel<<<289, 256, smem_bytes>>>(x, W, b, out);
}

// round 17
// speedup vs baseline: 1.3268x; 1.1780x over previous
#include <cuda_runtime.h>
#include <cuda_bf16.h>

#define NN 10
#define DD 64
#define MS 72

__device__ float g_M9[DD][DD];            // out = x @ g_M9 + g_dv9
__device__ float g_dv9[DD];
__device__ volatile unsigned g_flag;      // precompute-done counter (0..33)
__device__ unsigned g_done;               // gemm-block completion counter

__device__ __forceinline__ unsigned tf32_rna(float v) {
    unsigned u = __float_as_uint(v);
    return (u + 0x1000u) & 0xFFFFE000u;
}

__device__ __forceinline__ void mma_tf32(float& c0, float& c1, float& c2, float& c3,
                                         unsigned a0, unsigned a1, unsigned a2, unsigned a3,
                                         unsigned b0, unsigned b1) {
    asm volatile(
        "mma.sync.aligned.m16n8k8.row.col.f32.tf32.tf32.f32 "
        "{%0,%1,%2,%3}, {%4,%5,%6,%7}, {%8,%9}, {%0,%1,%2,%3};"
        : "+f"(c0), "+f"(c1), "+f"(c2), "+f"(c3)
        : "r"(a0), "r"(a1), "r"(a2), "r"(a3), "r"(b0), "r"(b1));
}

// ---- precompute role: blocks 0..32 (plain R8 body) --------------------------
__device__ void precompute_role(const float* __restrict__ W,
                                const float* __restrict__ B,
                                float* sh, int bi) {
    float* rowsh = sh;                    // [NN][2][DD]
    float* red   = sh + 1280;             // [16][2][DD]
    const int tid  = threadIdx.x;
    const bool bias = (bi == 32);
    const int d0   = bi * 2;
    const int kk   = tid >> 4;
    const int hg   = tid & 15;
    const int rr   = tid >> 6;
    const int hh   = tid & 63;

    if (tid < 128)
        rowsh[(0 * 2 + rr) * DD + hh] = (!bias && (d0 + rr == hh)) ? 1.f : 0.f;
    __syncthreads();

    #pragma unroll
    for (int t = 1; t <= 9; ++t) {
        float extra = 0.f;
        if (tid < 128) {
            if (!bias) {
                extra = W[((size_t)t * DD + (d0 + rr)) * DD + hh];
            } else if (rr == 0) {
                #pragma unroll
                for (int f = 0; f < t; ++f)
                    extra += B[((size_t)f * NN + t) * DD + hh];
            }
        }

        float4 a0 = make_float4(0.f, 0.f, 0.f, 0.f);
        float4 a1 = make_float4(0.f, 0.f, 0.f, 0.f);

        #pragma unroll
        for (int f = 1; f < t; ++f) {
            const float* Wb = W + (((size_t)f * NN + t) * DD + kk * 4) * DD + hg * 4;
            float4 w0 = *reinterpret_cast<const float4*>(Wb + 0 * DD);
            float4 w1 = *reinterpret_cast<const float4*>(Wb + 1 * DD);
            float4 w2 = *reinterpret_cast<const float4*>(Wb + 2 * DD);
            float4 w3 = *reinterpret_cast<const float4*>(Wb + 3 * DD);
            float4 r0 = *reinterpret_cast<const float4*>(&rowsh[(f * 2 + 0) * DD + kk * 4]);
            float4 r1 = *reinterpret_cast<const float4*>(&rowsh[(f * 2 + 1) * DD + kk * 4]);
            a0.x += r0.x * w0.x + r0.y * w1.x + r0.z * w2.x + r0.w * w3.x;
            a0.y += r0.x * w0.y + r0.y * w1.y + r0.z * w2.y + r0.w * w3.y;
            a0.z += r0.x * w0.z + r0.y * w1.z + r0.z * w2.z + r0.w * w3.z;
            a0.w += r0.x * w0.w + r0.y * w1.w + r0.z * w2.w + r0.w * w3.w;
            a1.x += r1.x * w0.x + r1.y * w1.x + r1.z * w2.x + r1.w * w3.x;
            a1.y += r1.x * w0.y + r1.y * w1.y + r1.z * w2.y + r1.w * w3.y;
            a1.z += r1.x * w0.z + r1.y * w1.z + r1.z * w2.z + r1.w * w3.z;
            a1.w += r1.x * w0.w + r1.y * w1.w + r1.z * w2.w + r1.w * w3.w;
        }
        *reinterpret_cast<float4*>(&red[(kk * 2 + 0) * DD + hg * 4]) = a0;
        *reinterpret_cast<float4*>(&red[(kk * 2 + 1) * DD + hg * 4]) = a1;
        __syncthreads();

        if (tid < 128) {
            float s = extra;
            #pragma unroll
            for (int k2 = 0; k2 < 16; ++k2) s += red[(k2 * 2 + rr) * DD + hh];
            rowsh[(t * 2 + rr) * DD + hh] = s;
            if (t == 9) {
                if (!bias)        g_M9[d0 + rr][hh] = s;
                else if (rr == 0) g_dv9[hh] = s;
            }
        }
        __syncthreads();
    }

    __threadfence();
    __syncthreads();
    if (tid == 0) atomicAdd((unsigned*)&g_flag, 1u);
}

// ---- gemm role: blocks 33..288, 256 rows each -------------------------------
// Identical to the 23.0 baseline EXCEPT the xs2 staging loop, now linear-
// coalesced (512B contiguous per warp instruction; same smem layout).
__device__ void gemm_role(const float* __restrict__ x, float* __restrict__ out,
                          unsigned* shb, int bid) {
    unsigned* Msm = shb;                                  // [64][MS]
    unsigned* xs2 = shb + 64 * MS;                        // [128][MS] tf32 half-2 rows
    float*    dvs = reinterpret_cast<float*>(xs2 + 128 * MS);
    const int tid  = threadIdx.x;
    const int w    = tid >> 5;
    const int lane = tid & 31;
    const int g    = lane >> 2;
    const int t    = lane & 3;
    const int R0   = bid * 256;
    const int rowA = R0 + w * 16 + g;                     // half-1 rows: rowA, rowA+8

    // ---- pre-wake 1: half-1 A fragments into registers ----
    unsigned af1[8][4];
    {
        const float2* a0p = reinterpret_cast<const float2*>(x + (size_t)rowA * DD);
        const float2* a1p = reinterpret_cast<const float2*>(x + (size_t)(rowA + 8) * DD);
        #pragma unroll
        for (int k8 = 0; k8 < 8; ++k8) {
            float2 v0 = a0p[4 * k8 + t];
            float2 v1 = a1p[4 * k8 + t];
            af1[k8][0] = tf32_rna(v0.x); af1[k8][2] = tf32_rna(v0.y);
            af1[k8][1] = tf32_rna(v1.x); af1[k8][3] = tf32_rna(v1.y);
        }
    }
    // ---- pre-wake 2: half-2 rows, LINEAR-COALESCED load -> tf32 -> smem ----
    {
        const float4* xsrc2 = reinterpret_cast<const float4*>(x + (size_t)(R0 + 128) * DD);
        #pragma unroll
        for (int i = 0; i < 8; ++i) {
            int c   = i * 256 + tid;                      // float4-chunk id, coalesced
            int row = c >> 4;                             // 0..127
            int col = (c & 15) * 4;
            float4 v = xsrc2[c];                          // 4 lines / warp-instr
            uint4 u = make_uint4(tf32_rna(v.x), tf32_rna(v.y), tf32_rna(v.z), tf32_rna(v.w));
            *reinterpret_cast<uint4*>(&xs2[row * MS + col]) = u;
        }
    }

    // ---- wait: single-thread spin, rest park at the barrier ----
    if (tid == 0) {
        while (g_flag < 33u) __nanosleep(64);
        __threadfence();
    }
    __syncthreads();

    // ---- stage M^T + bias ----
    {
        const float* Mflat = &g_M9[0][0];
        #pragma unroll
        for (int i = 0; i < 16; ++i) {
            int idx = i * 256 + tid;
            int k = idx >> 6, n = idx & 63;
            Msm[n * MS + k] = tf32_rna(Mflat[idx]);
        }
        if (tid < 64) dvs[tid] = g_dv9[tid];
    }
    __syncthreads();

    float2 dvp[8];
    #pragma unroll
    for (int n = 0; n < 8; ++n)
        dvp[n] = *reinterpret_cast<const float2*>(&dvs[8 * n + 2 * t]);

    // ---- half 1: A from registers ----
    {
        float acc[8][4];
        #pragma unroll
        for (int n = 0; n < 8; ++n)
            #pragma unroll
            for (int c = 0; c < 4; ++c) acc[n][c] = 0.f;
        #pragma unroll
        for (int k8 = 0; k8 < 8; ++k8) {
            const int kcol = 8 * k8 + 2 * t;
            #pragma unroll
            for (int n = 0; n < 8; ++n) {
                uint2 bf = *reinterpret_cast<const uint2*>(&Msm[(8 * n + g) * MS + kcol]);
                mma_tf32(acc[n][0], acc[n][1], acc[n][2], acc[n][3],
                         af1[k8][0], af1[k8][1], af1[k8][2], af1[k8][3], bf.x, bf.y);
            }
        }
        #pragma unroll
        for (int n = 0; n < 8; ++n) {
            float2 o0 = make_float2(acc[n][0] + dvp[n].x, acc[n][1] + dvp[n].y);
            float2 o1 = make_float2(acc[n][2] + dvp[n].x, acc[n][3] + dvp[n].y);
            *reinterpret_cast<float2*>(out + (size_t)rowA * DD + 8 * n + 2 * t)       = o0;
            *reinterpret_cast<float2*>(out + (size_t)(rowA + 8) * DD + 8 * n + 2 * t) = o1;
        }
    }
    // ---- half 2: A fragments from shared (conflict-free LDS.64) ----
    {
        const int lr = w * 16 + g;
        float acc[8][4];
        #pragma unroll
        for (int n = 0; n < 8; ++n)
            #pragma unroll
            for (int c = 0; c < 4; ++c) acc[n][c] = 0.f;
        #pragma unroll
        for (int k8 = 0; k8 < 8; ++k8) {
            const int kcol = 8 * k8 + 2 * t;
            uint2 a0 = *reinterpret_cast<const uint2*>(&xs2[lr * MS + kcol]);
            uint2 a1 = *reinterpret_cast<const uint2*>(&xs2[(lr + 8) * MS + kcol]);
            #pragma unroll
            for (int n = 0; n < 8; ++n) {
                uint2 bf = *reinterpret_cast<const uint2*>(&Msm[(8 * n + g) * MS + kcol]);
                mma_tf32(acc[n][0], acc[n][1], acc[n][2], acc[n][3],
                         a0.x, a1.x, a0.y, a1.y, bf.x, bf.y);
            }
        }
        const int rowB = R0 + 128 + lr;
        #pragma unroll
        for (int n = 0; n < 8; ++n) {
            float2 o0 = make_float2(acc[n][0] + dvp[n].x, acc[n][1] + dvp[n].y);
            float2 o1 = make_float2(acc[n][2] + dvp[n].x, acc[n][3] + dvp[n].y);
            *reinterpret_cast<float2*>(out + (size_t)rowB * DD + 8 * n + 2 * t)       = o0;
            *reinterpret_cast<float2*>(out + (size_t)(rowB + 8) * DD + 8 * n + 2 * t) = o1;
        }
    }

    // ---- replay hygiene: last gemm block resets the counters ----
    __syncthreads();
    if (tid == 0) {
        unsigned v = atomicAdd(&g_done, 1u);
        if (v == 255u) {
            g_done = 0u;
            g_flag = 0u;
            __threadfence();
        }
    }
}

__global__ __launch_bounds__(256, 2) void fused_kernel(const float* __restrict__ x,
                                                       const float* __restrict__ W,
                                                       const float* __restrict__ B,
                                                       float* __restrict__ out) {
    extern __shared__ __align__(16) float sh[];
    if (blockIdx.x < 33)
        precompute_role(W, B, sh, blockIdx.x);
    else
        gemm_role(x, out, reinterpret_cast<unsigned*>(sh), blockIdx.x - 33);
}

extern "C" void kernel_launch(void* const* d_in, const int* in_sizes, int n_in,
                              void* d_out, int out_size) {
    const float* x = (const float*)d_in[0];
    const float* W = (const float*)d_in[1];
    const float* b = (const float*)d_in[2];
    float* out = (float*)d_out;

    const int smem_bytes = (64 * MS + 128 * MS + 64) * 4;   // 55552
    cudaFuncSetAttribute(fused_kernel, cudaFuncAttributeMaxDynamicSharedMemorySize, smem_bytes);

    fused_kernel<<<289, 256, smem_bytes>>>(x, W, b, out);
}